// round 9
// baseline (speedup 1.0000x reference)
#include <cuda_runtime.h>
#include <cuda_bf16.h>

#define D 64
#define MAXN 100000
#define EPS 1e-5f

// Scratch: __device__ globals (allocation-free rule). 16B-aligned because we
// access them with float4 loads/stores and 128-bit RED.
__device__ __align__(16) float g_agg[(size_t)MAXN * D];
__device__ __align__(16) float g_xa[(size_t)MAXN * D];
__device__ __align__(16) float g_xb[(size_t)MAXN * D];
__device__ __align__(16) float g_ideg[MAXN];

// Buffer selectors (template constants)
#define BUF_EXT 0
#define BUF_XA  1
#define BUF_XB  2

template <int SEL>
__device__ __forceinline__ const float* pick_in(const float* ext) {
    if (SEL == BUF_XA) return g_xa;
    if (SEL == BUF_XB) return g_xb;
    return ext;
}
template <int SEL>
__device__ __forceinline__ float* pick_out(float* ext) {
    if (SEL == BUF_XA) return g_xa;
    if (SEL == BUF_XB) return g_xb;
    return ext;
}

// ---------------------------------------------------------------------------
// Vector atomic reduction: one 16B RED instead of 4 scalar atomics
__device__ __forceinline__ void red_add_f32x4(float4* addr, float4 v) {
    asm volatile("red.global.add.v4.f32 [%0], {%1, %2, %3, %4};"
                 :: "l"(addr), "f"(v.x), "f"(v.y), "f"(v.z), "f"(v.w)
                 : "memory");
}

// ---------------------------------------------------------------------------
__global__ void zero_kernel(int n4, int nNodes) {
    int i = blockIdx.x * blockDim.x + threadIdx.x;
    int stride = gridDim.x * blockDim.x;
    float4 z = make_float4(0.f, 0.f, 0.f, 0.f);
    float4* a4 = (float4*)g_agg;
    for (int j = i; j < n4; j += stride) a4[j] = z;
    for (int j = i; j < nNodes; j += stride) g_ideg[j] = 0.f;
}

__global__ void deg_kernel(const int* __restrict__ dst, int E) {
    int i = blockIdx.x * blockDim.x + threadIdx.x;
    if (i < E) atomicAdd(&g_ideg[dst[i]], 1.0f);
}

__global__ void invdeg_kernel(int n) {
    int i = blockIdx.x * blockDim.x + threadIdx.x;
    if (i < n) {
        float d = g_ideg[i];
        g_ideg[i] = (d > 0.f) ? (1.0f / d) : 0.0f;
    }
}

// 16 threads per edge, one float4 per thread. Gather x[src] (L2-resident),
// RED.v4 into g_agg[dst].
template <int IN>
__global__ void scatter_kernel(const float* __restrict__ ext,
                               const int* __restrict__ src,
                               const int* __restrict__ dst, int E) {
    const float* x = pick_in<IN>(ext);
    int i = blockIdx.x * blockDim.x + threadIdx.x;
    int e = i >> 4;
    int c = i & 15;
    if (e >= E) return;
    int s = src[e];
    int d = dst[e];
    float4 v = ((const float4*)(x + (size_t)s * D))[c];
    red_add_f32x4(((float4*)(g_agg + (size_t)d * D)) + c, v);
}

// ---------------------------------------------------------------------------
// Generic matvec: out[n] = x[n] @ W + b. Used for the L0 residual projection
// (ext x -> g_xb) and the final FC (g_xa -> d_out).
template <int IN, int OUT>
__global__ void matmul_kernel(const float* __restrict__ extIn,
                              float* __restrict__ extOut,
                              const float* __restrict__ w,
                              const float* __restrict__ b, int nNodes) {
    const float* x = pick_in<IN>(extIn);
    float* out = pick_out<OUT>(extOut);

    extern __shared__ float sW[];
    __shared__ float sX[4][D];

    int tid = threadIdx.x;
    {
        const float4* w4 = (const float4*)w;
        float4* s4 = (float4*)sW;
        for (int i = tid; i < (D * D) / 4; i += blockDim.x) s4[i] = w4[i];
    }
    __syncthreads();

    int ln = tid >> 6;
    int col = tid & 63;
    float bv = b[col];

    int numTiles = (nNodes + 3) >> 2;
    for (int tile = blockIdx.x; tile < numTiles; tile += gridDim.x) {
        int n = tile * 4 + ln;
        bool valid = (n < nNodes);
        float xv = valid ? x[(size_t)n * D + col] : 0.f;
        __syncthreads();
        sX[ln][col] = xv;
        __syncthreads();
        float acc = bv;
        #pragma unroll
        for (int k = 0; k < D; k++)
            acc = fmaf(sX[ln][k], sW[k * D + col], acc);
        if (valid) out[(size_t)n * D + col] = acc;
    }
}

// ---------------------------------------------------------------------------
// Fused per-node kernel: h = agg*inv_deg @ Wl + b + x @ Wr; LN; ReLU; +residual.
// Block = 256 threads = 4 nodes x 64 cols. Wl/Wr staged in 32KB dynamic smem.
// Residual: read from g_xb when RES_FROM_XB (layer 0), else residual = x.
// Also zeroes agg in-place for the next layer's scatter.
template <bool RES_FROM_XB, int IN, int OUT>
__global__ void node_kernel(const float* __restrict__ ext,
                            const float* __restrict__ wl,
                            const float* __restrict__ bl,
                            const float* __restrict__ wr,
                            const float* __restrict__ gamma,
                            const float* __restrict__ beta,
                            int nNodes) {
    const float* x = pick_in<IN>(ext);
    float* xout = pick_out<OUT>(nullptr);
    float* agg = g_agg;

    extern __shared__ float sW[];
    float* sWl = sW;
    float* sWr = sW + D * D;

    __shared__ float sX[4][D];
    __shared__ float sA[4][D];
    __shared__ float sRed[4][2][2];  // [node][half-warp][sum, sumsq]

    int tid = threadIdx.x;

    // Stage weights (row-major [k][j]) as float4
    {
        const float4* wl4 = (const float4*)wl;
        const float4* wr4 = (const float4*)wr;
        float4* sl4 = (float4*)sWl;
        float4* sr4 = (float4*)sWr;
        for (int i = tid; i < (D * D) / 4; i += blockDim.x) {
            sl4[i] = wl4[i];
            sr4[i] = wr4[i];
        }
    }
    __syncthreads();

    int ln = tid >> 6;        // local node 0..3
    int col = tid & 63;       // output column
    int half = col >> 5;      // which warp-half of the node

    float blv = bl[col];
    float gv = gamma[col];
    float bev = beta[col];

    int numTiles = (nNodes + 3) >> 2;
    for (int tile = blockIdx.x; tile < numTiles; tile += gridDim.x) {
        int n = tile * 4 + ln;
        bool valid = (n < nNodes);
        float xv = 0.f, av = 0.f, r = 0.f;
        if (valid) {
            size_t off = (size_t)n * D + col;
            xv = x[off];
            av = agg[off] * g_ideg[n];
            agg[off] = 0.f;  // prep agg for the next layer's scatter
            r = RES_FROM_XB ? g_xb[off] : xv;
        }
        __syncthreads();  // prior iteration's smem reads complete
        sX[ln][col] = xv;
        sA[ln][col] = av;
        __syncthreads();

        float acc = blv;
        #pragma unroll
        for (int k = 0; k < D; k++) {
            acc = fmaf(sA[ln][k], sWl[k * D + col], acc);
            acc = fmaf(sX[ln][k], sWr[k * D + col], acc);
        }

        // LayerNorm over this node's 64 h values (2 warps per node)
        float s = acc, s2 = acc * acc;
        #pragma unroll
        for (int o = 16; o > 0; o >>= 1) {
            s += __shfl_xor_sync(0xFFFFFFFFu, s, o);
            s2 += __shfl_xor_sync(0xFFFFFFFFu, s2, o);
        }
        if ((col & 31) == 0) {
            sRed[ln][half][0] = s;
            sRed[ln][half][1] = s2;
        }
        __syncthreads();
        float sum = sRed[ln][0][0] + sRed[ln][1][0];
        float sum2 = sRed[ln][0][1] + sRed[ln][1][1];
        float mu = sum * (1.0f / 64.0f);
        float var = sum2 * (1.0f / 64.0f) - mu * mu;
        float rstd = rsqrtf(var + EPS);
        float y = (acc - mu) * rstd * gv + bev;
        y = fmaxf(y, 0.f) + r;
        if (valid) xout[(size_t)n * D + col] = y;
    }
}

// ---------------------------------------------------------------------------
extern "C" void kernel_launch(void* const* d_in, const int* in_sizes, int n_in,
                              void* d_out, int out_size) {
    const float* x     = (const float*)d_in[0];
    const int*   esrc  = (const int*)d_in[1];
    const int*   edst  = (const int*)d_in[2];
    const float* w_l   = (const float*)d_in[3];
    const float* b_l   = (const float*)d_in[4];
    const float* w_r   = (const float*)d_in[5];
    const float* gamma = (const float*)d_in[6];
    const float* beta  = (const float*)d_in[7];
    const float* w_res = (const float*)d_in[8];
    const float* b_res = (const float*)d_in[9];
    const float* w_fc  = (const float*)d_in[10];
    const float* b_fc  = (const float*)d_in[11];
    float* out = (float*)d_out;

    int N = in_sizes[0] / D;
    int E = in_sizes[1];

    const int T = 256;
    int scatterBlocks = (E * 16 + T - 1) / T;
    const int NODE_BLOCKS = 888;  // ~6 blocks/SM at 32KB+static smem
    const size_t SMEM_NODE = 2 * D * D * sizeof(float);   // 32KB
    const size_t SMEM_MM   = D * D * sizeof(float);       // 16KB

    // degrees + zero agg
    zero_kernel<<<2048, T>>>((N * D) / 4, N);
    deg_kernel<<<(E + T - 1) / T, T>>>(edst, E);
    invdeg_kernel<<<(N + T - 1) / T, T>>>(N);

    // L0 residual projection: g_xb = x @ w_res + b_res
    matmul_kernel<BUF_EXT, BUF_XB><<<NODE_BLOCKS, T, SMEM_MM>>>(
        x, nullptr, w_res, b_res, N);

    // Layer 0: scatter(x) -> node -> g_xa  (residual from g_xb)
    scatter_kernel<BUF_EXT><<<scatterBlocks, T>>>(x, esrc, edst, E);
    node_kernel<true, BUF_EXT, BUF_XA><<<NODE_BLOCKS, T, SMEM_NODE>>>(
        x, w_l, b_l, w_r, gamma, beta, N);

    // Layer 1: g_xa -> g_xb  (residual = x itself)
    scatter_kernel<BUF_XA><<<scatterBlocks, T>>>(nullptr, esrc, edst, E);
    node_kernel<false, BUF_XA, BUF_XB><<<NODE_BLOCKS, T, SMEM_NODE>>>(
        nullptr, w_l + D * D, b_l + D, w_r + D * D, gamma + D, beta + D, N);

    // Layer 2: g_xb -> g_xa
    scatter_kernel<BUF_XB><<<scatterBlocks, T>>>(nullptr, esrc, edst, E);
    node_kernel<false, BUF_XB, BUF_XA><<<NODE_BLOCKS, T, SMEM_NODE>>>(
        nullptr, w_l + 2 * D * D, b_l + 2 * D, w_r + 2 * D * D,
        gamma + 2 * D, beta + 2 * D, N);

    // Final FC: out = g_xa @ w_fc + b_fc
    matmul_kernel<BUF_XA, BUF_EXT><<<NODE_BLOCKS, T, SMEM_MM>>>(
        nullptr, out, w_fc, b_fc, N);
}

// round 11
// speedup vs baseline: 1.7506x; 1.7506x over previous
#include <cuda_runtime.h>
#include <cuda_bf16.h>

#define D 64
#define MAXN 100000
#define EPS 1e-5f
#define TILE_NODES 32   // nodes per block iteration
#define NPT 8           // nodes per 64-thread group (4 groups per block)

// Scratch: __device__ globals, 16B-aligned (float4 / RED.128 access)
__device__ __align__(16) float g_agg[(size_t)MAXN * D];
__device__ __align__(16) float g_xa[(size_t)MAXN * D];
__device__ __align__(16) float g_xb[(size_t)MAXN * D];
__device__ __align__(16) float g_ideg[MAXN];

#define BUF_EXT 0
#define BUF_XA  1
#define BUF_XB  2

template <int SEL>
__device__ __forceinline__ const float* pick_in(const float* ext) {
    if (SEL == BUF_XA) return g_xa;
    if (SEL == BUF_XB) return g_xb;
    return ext;
}

// ---------------------------------------------------------------------------
__device__ __forceinline__ void red_add_f32x4(float4* addr, float4 v) {
    asm volatile("red.global.add.v4.f32 [%0], {%1, %2, %3, %4};"
                 :: "l"(addr), "f"(v.x), "f"(v.y), "f"(v.z), "f"(v.w)
                 : "memory");
}

// ---------------------------------------------------------------------------
__global__ void zero_kernel(int n4, int nNodes) {
    int i = blockIdx.x * blockDim.x + threadIdx.x;
    int stride = gridDim.x * blockDim.x;
    float4 z = make_float4(0.f, 0.f, 0.f, 0.f);
    float4* a4 = (float4*)g_agg;
    for (int j = i; j < n4; j += stride) a4[j] = z;
    for (int j = i; j < nNodes; j += stride) g_ideg[j] = 0.f;
}

__global__ void deg_kernel(const int* __restrict__ dst, int E) {
    int i = blockIdx.x * blockDim.x + threadIdx.x;
    if (i < E) atomicAdd(&g_ideg[dst[i]], 1.0f);
}

__global__ void invdeg_kernel(int n) {
    int i = blockIdx.x * blockDim.x + threadIdx.x;
    if (i < n) {
        float d = g_ideg[i];
        g_ideg[i] = (d > 0.f) ? (1.0f / d) : 0.0f;
    }
}

// 16 threads per edge, one float4 each: gather x[src] row (256B contiguous),
// RED.v4 into g_agg[dst].
template <int IN>
__global__ void scatter_kernel(const float* __restrict__ ext,
                               const int* __restrict__ src,
                               const int* __restrict__ dst, int E) {
    const float* x = pick_in<IN>(ext);
    int i = blockIdx.x * blockDim.x + threadIdx.x;
    int e = i >> 4;
    int c = i & 15;
    if (e >= E) return;
    int s = src[e];
    int d = dst[e];
    float4 v = ((const float4*)(x + (size_t)s * D))[c];
    red_add_f32x4(((float4*)(g_agg + (size_t)d * D)) + c, v);
}

// ---------------------------------------------------------------------------
// Fused node kernel, register-tiled: block = 256 thr = 4 groups x 64 cols.
// Each group computes NPT=8 nodes; W values are loaded once from smem and
// reused across the 8 nodes (registers), x/a come in as float4 broadcasts.
//
// MODE 0: layer 0.  in = ext x, out = g_xa. Residual = x @ w_res + b_res,
//         computed as a fused third accumulator (sWe = w_res).
// MODE 1: layer 1.  in = g_xa, out = g_xb. Residual = input x.
// MODE 2: layer 2 + final FC. in = g_xb. Residual = input x. After LN, y is
//         staged in smem and multiplied by sWe = w_fc; writes ext_out.
// MODE 0/1 also zero g_agg for the next scatter.
//
// NOTE: static+dynamic smem exceeds the 48KB default envelope; host side must
// opt in via cudaFuncSetAttribute(MaxDynamicSharedMemorySize).
template <int MODE>
__global__ __launch_bounds__(256)
void node_kernel(const float* __restrict__ ext_in,
                 float* __restrict__ ext_out,
                 const float* __restrict__ wl,
                 const float* __restrict__ bl,
                 const float* __restrict__ wr,
                 const float* __restrict__ gamma,
                 const float* __restrict__ beta,
                 const float* __restrict__ we,
                 const float* __restrict__ be,
                 int nNodes) {
    const float* x = (MODE == 0) ? ext_in : (MODE == 1 ? (const float*)g_xa
                                                       : (const float*)g_xb);
    float* xout = (MODE == 0) ? g_xa : (MODE == 1 ? g_xb : ext_out);

    extern __shared__ __align__(16) float sW[];   // sWl [64][64], sWr [64][64]
    float* sWl = sW;
    float* sWr = sW + D * D;
    __shared__ __align__(16) float sX[TILE_NODES][D];
    __shared__ __align__(16) float sA[TILE_NODES][D];
    __shared__ float sRed[4][2][NPT][2];
    __shared__ __align__(16) float sWe[(MODE != 1) ? (D * D) : 4];

    int tid = threadIdx.x;

    // Stage weights
    for (int i = tid; i < (D * D) / 4; i += 256) {
        ((float4*)sWl)[i] = ((const float4*)wl)[i];
        ((float4*)sWr)[i] = ((const float4*)wr)[i];
        if (MODE != 1) ((float4*)sWe)[i] = ((const float4*)we)[i];
    }

    int col = tid & 63;
    int grp = tid >> 6;
    int lane = tid & 31;
    int half = (tid >> 5) & 1;
    int nb = grp * NPT;   // first local node for this group

    float blv = bl[col];
    float gv = gamma[col];
    float bev = beta[col];
    float bev2 = (MODE != 1) ? be[col] : 0.f;

    int numTiles = (nNodes + TILE_NODES - 1) / TILE_NODES;
    for (int tile = blockIdx.x; tile < numTiles; tile += gridDim.x) {
        int base = tile * TILE_NODES;

        __syncthreads();  // previous iteration's smem reads complete
        // Load 32 node rows of x and agg (float4-linear), scale by inv_deg,
        // zero agg for next scatter.
        for (int i = tid; i < (TILE_NODES * D) / 4; i += 256) {
            int row = base + (i >> 4);
            float4 xv = make_float4(0.f, 0.f, 0.f, 0.f);
            float4 av = xv;
            if (row < nNodes) {
                size_t o4 = (size_t)row * (D / 4) + (i & 15);
                xv = ((const float4*)x)[o4];
                float4 t = ((float4*)g_agg)[o4];
                float id = g_ideg[row];
                av = make_float4(t.x * id, t.y * id, t.z * id, t.w * id);
                if (MODE != 2)
                    ((float4*)g_agg)[o4] = make_float4(0.f, 0.f, 0.f, 0.f);
            }
            ((float4*)sX)[i] = xv;
            ((float4*)sA)[i] = av;
        }
        __syncthreads();

        float acc[NPT], acc2[NPT];
        #pragma unroll
        for (int j = 0; j < NPT; j++) {
            acc[j] = blv;
            acc2[j] = (MODE == 0) ? bev2 : 0.f;
        }

        #pragma unroll 4
        for (int k4 = 0; k4 < D / 4; k4++) {
            int k = k4 * 4;
            float wl0 = sWl[(k + 0) * D + col];
            float wl1 = sWl[(k + 1) * D + col];
            float wl2 = sWl[(k + 2) * D + col];
            float wl3 = sWl[(k + 3) * D + col];
            float wr0 = sWr[(k + 0) * D + col];
            float wr1 = sWr[(k + 1) * D + col];
            float wr2 = sWr[(k + 2) * D + col];
            float wr3 = sWr[(k + 3) * D + col];
            float we0, we1, we2, we3;
            if (MODE == 0) {
                we0 = sWe[(k + 0) * D + col];
                we1 = sWe[(k + 1) * D + col];
                we2 = sWe[(k + 2) * D + col];
                we3 = sWe[(k + 3) * D + col];
            }
            #pragma unroll
            for (int j = 0; j < NPT; j++) {
                float4 a = ((const float4*)sA[nb + j])[k4];   // broadcast
                float4 xx = ((const float4*)sX[nb + j])[k4];  // broadcast
                acc[j] = fmaf(a.x, wl0, acc[j]);
                acc[j] = fmaf(a.y, wl1, acc[j]);
                acc[j] = fmaf(a.z, wl2, acc[j]);
                acc[j] = fmaf(a.w, wl3, acc[j]);
                acc[j] = fmaf(xx.x, wr0, acc[j]);
                acc[j] = fmaf(xx.y, wr1, acc[j]);
                acc[j] = fmaf(xx.z, wr2, acc[j]);
                acc[j] = fmaf(xx.w, wr3, acc[j]);
                if (MODE == 0) {
                    acc2[j] = fmaf(xx.x, we0, acc2[j]);
                    acc2[j] = fmaf(xx.y, we1, acc2[j]);
                    acc2[j] = fmaf(xx.z, we2, acc2[j]);
                    acc2[j] = fmaf(xx.w, we3, acc2[j]);
                }
            }
        }

        // LayerNorm: per-node reduction across the group's 64 threads
        #pragma unroll
        for (int j = 0; j < NPT; j++) {
            float s = acc[j], s2 = acc[j] * acc[j];
            #pragma unroll
            for (int o = 16; o > 0; o >>= 1) {
                s += __shfl_xor_sync(0xFFFFFFFFu, s, o);
                s2 += __shfl_xor_sync(0xFFFFFFFFu, s2, o);
            }
            if (lane == 0) {
                sRed[grp][half][j][0] = s;
                sRed[grp][half][j][1] = s2;
            }
        }
        __syncthreads();

        #pragma unroll
        for (int j = 0; j < NPT; j++) {
            float sum = sRed[grp][0][j][0] + sRed[grp][1][j][0];
            float sum2 = sRed[grp][0][j][1] + sRed[grp][1][j][1];
            float mu = sum * (1.0f / 64.0f);
            float var = sum2 * (1.0f / 64.0f) - mu * mu;
            float rstd = rsqrtf(var + EPS);
            float y = (acc[j] - mu) * rstd * gv + bev;
            y = fmaxf(y, 0.f);
            // residual
            if (MODE == 0) y += acc2[j];
            else           y += sX[nb + j][col];

            if (MODE != 2) {
                int n = base + nb + j;
                if (n < nNodes) xout[(size_t)n * D + col] = y;
            } else {
                sA[nb + j][col] = y;  // stage for fused FC (post-sync safe)
            }
        }

        if (MODE == 2) {
            __syncthreads();
            float acc3[NPT];
            #pragma unroll
            for (int j = 0; j < NPT; j++) acc3[j] = bev2;
            #pragma unroll 4
            for (int k4 = 0; k4 < D / 4; k4++) {
                int k = k4 * 4;
                float w0 = sWe[(k + 0) * D + col];
                float w1 = sWe[(k + 1) * D + col];
                float w2 = sWe[(k + 2) * D + col];
                float w3 = sWe[(k + 3) * D + col];
                #pragma unroll
                for (int j = 0; j < NPT; j++) {
                    float4 yy = ((const float4*)sA[nb + j])[k4];
                    acc3[j] = fmaf(yy.x, w0, acc3[j]);
                    acc3[j] = fmaf(yy.y, w1, acc3[j]);
                    acc3[j] = fmaf(yy.z, w2, acc3[j]);
                    acc3[j] = fmaf(yy.w, w3, acc3[j]);
                }
            }
            #pragma unroll
            for (int j = 0; j < NPT; j++) {
                int n = base + nb + j;
                if (n < nNodes) xout[(size_t)n * D + col] = acc3[j];
            }
        }
    }
}

// ---------------------------------------------------------------------------
extern "C" void kernel_launch(void* const* d_in, const int* in_sizes, int n_in,
                              void* d_out, int out_size) {
    const float* x     = (const float*)d_in[0];
    const int*   esrc  = (const int*)d_in[1];
    const int*   edst  = (const int*)d_in[2];
    const float* w_l   = (const float*)d_in[3];
    const float* b_l   = (const float*)d_in[4];
    const float* w_r   = (const float*)d_in[5];
    const float* gamma = (const float*)d_in[6];
    const float* beta  = (const float*)d_in[7];
    const float* w_res = (const float*)d_in[8];
    const float* b_res = (const float*)d_in[9];
    const float* w_fc  = (const float*)d_in[10];
    const float* b_fc  = (const float*)d_in[11];
    float* out = (float*)d_out;

    int N = in_sizes[0] / D;
    int E = in_sizes[1];

    const int T = 256;
    int scatterBlocks = (E * 16 + T - 1) / T;
    const size_t SMEM_NODE = 2 * D * D * sizeof(float);  // 32KB dynamic
    const int BLK_FUSED = 444;   // 3 blocks/SM at ~65KB total smem
    const int BLK_MID   = 592;   // 4 blocks/SM at ~49KB total smem

    // Opt-in: static+dynamic smem of node kernels exceeds the 48KB default.
    // cudaFuncSetAttribute is not a stream op — legal during graph capture.
    static bool attr_done = false;
    if (!attr_done) {
        cudaFuncSetAttribute(node_kernel<0>,
                             cudaFuncAttributeMaxDynamicSharedMemorySize,
                             (int)SMEM_NODE);
        cudaFuncSetAttribute(node_kernel<1>,
                             cudaFuncAttributeMaxDynamicSharedMemorySize,
                             (int)SMEM_NODE);
        cudaFuncSetAttribute(node_kernel<2>,
                             cudaFuncAttributeMaxDynamicSharedMemorySize,
                             (int)SMEM_NODE);
        attr_done = true;
    }

    // prolog: zero agg + degrees
    zero_kernel<<<2048, T>>>((N * D) / 4, N);
    deg_kernel<<<(E + T - 1) / T, T>>>(edst, E);
    invdeg_kernel<<<(N + T - 1) / T, T>>>(N);

    // Layer 0: scatter(x); node (fused residual projection) -> g_xa
    scatter_kernel<BUF_EXT><<<scatterBlocks, T>>>(x, esrc, edst, E);
    node_kernel<0><<<BLK_FUSED, T, SMEM_NODE>>>(
        x, nullptr, w_l, b_l, w_r, gamma, beta, w_res, b_res, N);

    // Layer 1: scatter(g_xa); node -> g_xb
    scatter_kernel<BUF_XA><<<scatterBlocks, T>>>(nullptr, esrc, edst, E);
    node_kernel<1><<<BLK_MID, T, SMEM_NODE>>>(
        nullptr, nullptr, w_l + D * D, b_l + D, w_r + D * D,
        gamma + D, beta + D, nullptr, nullptr, N);

    // Layer 2 + final FC: scatter(g_xb); node writes d_out directly
    scatter_kernel<BUF_XB><<<scatterBlocks, T>>>(nullptr, esrc, edst, E);
    node_kernel<2><<<BLK_FUSED, T, SMEM_NODE>>>(
        nullptr, out, w_l + 2 * D * D, b_l + 2 * D, w_r + 2 * D * D,
        gamma + 2 * D, beta + 2 * D, w_fc, b_fc, N);
}

// round 12
// speedup vs baseline: 2.4386x; 1.3930x over previous
#include <cuda_runtime.h>
#include <cuda_bf16.h>

#define D 64
#define MAXN 100000
#define MAXE 1600000
#define EPS 1e-5f
#define TILE_NODES 32   // nodes per block iteration (node kernel)
#define NPT 8           // nodes per 64-thread group (4 groups per block)

// Scratch: __device__ globals, 16B-aligned (float4 access)
__device__ __align__(16) float g_agg[(size_t)MAXN * D];
__device__ __align__(16) float g_xa[(size_t)MAXN * D];
__device__ __align__(16) float g_xb[(size_t)MAXN * D];
__device__ __align__(16) float g_ideg[MAXN];

// CSR-by-destination scratch
__device__ int g_count[MAXN];
__device__ int g_rowptr[MAXN + 1];
__device__ int g_cursor[MAXN];
__device__ int g_esrc[MAXE];
__device__ int g_bsum[256];

#define BUF_EXT 0
#define BUF_XA  1
#define BUF_XB  2

template <int SEL>
__device__ __forceinline__ const float* pick_in(const float* ext) {
    if (SEL == BUF_XA) return g_xa;
    if (SEL == BUF_XB) return g_xb;
    return ext;
}

// ---------------------------------------------------------------------------
// CSR build
// ---------------------------------------------------------------------------
__global__ void zcnt_kernel(int n) {
    int i = blockIdx.x * blockDim.x + threadIdx.x;
    if (i < n) g_count[i] = 0;
}

__global__ void deg_kernel(const int* __restrict__ dst, int E) {
    int i = blockIdx.x * blockDim.x + threadIdx.x;
    if (i < E) atomicAdd(&g_count[dst[i]], 1);
}

// Phase A: per-block (1024 counts) sums
__global__ void scanA_kernel(int nNodes) {
    __shared__ int s[256];
    int b = blockIdx.x, t = threadIdx.x;
    int base = b * 1024 + t * 4;
    int tot = 0;
    #pragma unroll
    for (int k = 0; k < 4; k++)
        if (base + k < nNodes) tot += g_count[base + k];
    s[t] = tot;
    __syncthreads();
    for (int off = 128; off > 0; off >>= 1) {
        if (t < off) s[t] += s[t + off];
        __syncthreads();
    }
    if (t == 0) g_bsum[b] = s[0];
}

// Phase B: exclusive scan of block sums (single block, <=256 entries)
__global__ void scanB_kernel(int nb) {
    __shared__ int s[256];
    int t = threadIdx.x;
    s[t] = (t < nb) ? g_bsum[t] : 0;
    __syncthreads();
    for (int off = 1; off < 256; off <<= 1) {
        int y = (t >= off) ? s[t - off] : 0;
        __syncthreads();
        s[t] += y;
        __syncthreads();
    }
    g_bsum[t] = (t > 0) ? s[t - 1] : 0;
}

// Phase C: full exclusive scan -> rowptr + cursor + inv_deg
__global__ void scanC_kernel(int nNodes) {
    __shared__ int s[256];
    int b = blockIdx.x, t = threadIdx.x;
    int base = b * 1024 + t * 4;
    int c[4];
    #pragma unroll
    for (int k = 0; k < 4; k++)
        c[k] = (base + k < nNodes) ? g_count[base + k] : 0;
    int tot = c[0] + c[1] + c[2] + c[3];
    s[t] = tot;
    __syncthreads();
    for (int off = 1; off < 256; off <<= 1) {
        int y = (t >= off) ? s[t - off] : 0;
        __syncthreads();
        s[t] += y;
        __syncthreads();
    }
    int ex = ((t > 0) ? s[t - 1] : 0) + g_bsum[b];
    int p[4];
    p[0] = ex;
    p[1] = p[0] + c[0];
    p[2] = p[1] + c[1];
    p[3] = p[2] + c[2];
    #pragma unroll
    for (int k = 0; k < 4; k++) {
        int idx = base + k;
        if (idx <= nNodes) g_rowptr[idx] = p[k];
        if (idx < nNodes) {
            g_cursor[idx] = p[k];
            g_ideg[idx] = (c[k] > 0) ? (1.0f / (float)c[k]) : 0.0f;
        }
    }
}

__global__ void fill_kernel(const int* __restrict__ src,
                            const int* __restrict__ dst, int E) {
    int i = blockIdx.x * blockDim.x + threadIdx.x;
    if (i < E) {
        int d = dst[i];
        int p = atomicAdd(&g_cursor[d], 1);
        g_esrc[p] = src[i];
    }
}

// ---------------------------------------------------------------------------
// Pull-mode aggregation: 16-thread group per dst node, no atomics.
// Each thread owns one float4 column; walk the node's CSR edge list,
// accumulate x[src] rows (256B coalesced across the group), scale by 1/deg.
// ---------------------------------------------------------------------------
template <int IN>
__global__ __launch_bounds__(256)
void agg_kernel(const float* __restrict__ ext, int nNodes) {
    const float* x = pick_in<IN>(ext);
    const float4* x4 = (const float4*)x;
    int t = threadIdx.x;
    int c = t & 15;
    int g = t >> 4;
    int n = blockIdx.x * 16 + g;
    if (n >= nNodes) return;

    int start = g_rowptr[n];
    int end = g_rowptr[n + 1];

    float4 a0 = make_float4(0.f, 0.f, 0.f, 0.f);
    float4 a1 = make_float4(0.f, 0.f, 0.f, 0.f);
    int i = start;
    for (; i + 1 < end; i += 2) {
        int s0 = __ldg(&g_esrc[i]);
        int s1 = __ldg(&g_esrc[i + 1]);
        float4 v0 = x4[(size_t)s0 * 16 + c];
        float4 v1 = x4[(size_t)s1 * 16 + c];
        a0.x += v0.x; a0.y += v0.y; a0.z += v0.z; a0.w += v0.w;
        a1.x += v1.x; a1.y += v1.y; a1.z += v1.z; a1.w += v1.w;
    }
    if (i < end) {
        int s0 = __ldg(&g_esrc[i]);
        float4 v0 = x4[(size_t)s0 * 16 + c];
        a0.x += v0.x; a0.y += v0.y; a0.z += v0.z; a0.w += v0.w;
    }
    float id = g_ideg[n];
    float4 r = make_float4((a0.x + a1.x) * id, (a0.y + a1.y) * id,
                           (a0.z + a1.z) * id, (a0.w + a1.w) * id);
    ((float4*)g_agg)[(size_t)n * 16 + c] = r;
}

// ---------------------------------------------------------------------------
// Fused node kernel, register-tiled (unchanged from R11 except: no agg zeroing)
// MODE 0: L0, in=ext x, out=g_xa, residual = x@w_res+b_res (fused 3rd acc).
// MODE 1: L1, in=g_xa, out=g_xb, residual = input.
// MODE 2: L2+FC, in=g_xb, writes ext_out = (LN-out) @ w_fc + b_fc.
template <int MODE>
__global__ __launch_bounds__(256)
void node_kernel(const float* __restrict__ ext_in,
                 float* __restrict__ ext_out,
                 const float* __restrict__ wl,
                 const float* __restrict__ bl,
                 const float* __restrict__ wr,
                 const float* __restrict__ gamma,
                 const float* __restrict__ beta,
                 const float* __restrict__ we,
                 const float* __restrict__ be,
                 int nNodes) {
    const float* x = (MODE == 0) ? ext_in : (MODE == 1 ? (const float*)g_xa
                                                       : (const float*)g_xb);
    float* xout = (MODE == 0) ? g_xa : (MODE == 1 ? g_xb : ext_out);

    extern __shared__ __align__(16) float sW[];   // sWl[64][64], sWr[64][64]
    float* sWl = sW;
    float* sWr = sW + D * D;
    __shared__ __align__(16) float sX[TILE_NODES][D];
    __shared__ __align__(16) float sA[TILE_NODES][D];
    __shared__ float sRed[4][2][NPT][2];
    __shared__ __align__(16) float sWe[(MODE != 1) ? (D * D) : 4];

    int tid = threadIdx.x;

    for (int i = tid; i < (D * D) / 4; i += 256) {
        ((float4*)sWl)[i] = ((const float4*)wl)[i];
        ((float4*)sWr)[i] = ((const float4*)wr)[i];
        if (MODE != 1) ((float4*)sWe)[i] = ((const float4*)we)[i];
    }

    int col = tid & 63;
    int grp = tid >> 6;
    int lane = tid & 31;
    int half = (tid >> 5) & 1;
    int nb = grp * NPT;

    float blv = bl[col];
    float gv = gamma[col];
    float bev = beta[col];
    float bev2 = (MODE != 1) ? be[col] : 0.f;

    int numTiles = (nNodes + TILE_NODES - 1) / TILE_NODES;
    for (int tile = blockIdx.x; tile < numTiles; tile += gridDim.x) {
        int base = tile * TILE_NODES;

        __syncthreads();
        for (int i = tid; i < (TILE_NODES * D) / 4; i += 256) {
            int row = base + (i >> 4);
            float4 xv = make_float4(0.f, 0.f, 0.f, 0.f);
            float4 av = xv;
            if (row < nNodes) {
                size_t o4 = (size_t)row * (D / 4) + (i & 15);
                xv = ((const float4*)x)[o4];
                av = ((const float4*)g_agg)[o4];
            }
            ((float4*)sX)[i] = xv;
            ((float4*)sA)[i] = av;
        }
        __syncthreads();

        float acc[NPT], acc2[NPT];
        #pragma unroll
        for (int j = 0; j < NPT; j++) {
            acc[j] = blv;
            acc2[j] = (MODE == 0) ? bev2 : 0.f;
        }

        #pragma unroll 4
        for (int k4 = 0; k4 < D / 4; k4++) {
            int k = k4 * 4;
            float wl0 = sWl[(k + 0) * D + col];
            float wl1 = sWl[(k + 1) * D + col];
            float wl2 = sWl[(k + 2) * D + col];
            float wl3 = sWl[(k + 3) * D + col];
            float wr0 = sWr[(k + 0) * D + col];
            float wr1 = sWr[(k + 1) * D + col];
            float wr2 = sWr[(k + 2) * D + col];
            float wr3 = sWr[(k + 3) * D + col];
            float we0, we1, we2, we3;
            if (MODE == 0) {
                we0 = sWe[(k + 0) * D + col];
                we1 = sWe[(k + 1) * D + col];
                we2 = sWe[(k + 2) * D + col];
                we3 = sWe[(k + 3) * D + col];
            }
            #pragma unroll
            for (int j = 0; j < NPT; j++) {
                float4 a = ((const float4*)sA[nb + j])[k4];
                float4 xx = ((const float4*)sX[nb + j])[k4];
                acc[j] = fmaf(a.x, wl0, acc[j]);
                acc[j] = fmaf(a.y, wl1, acc[j]);
                acc[j] = fmaf(a.z, wl2, acc[j]);
                acc[j] = fmaf(a.w, wl3, acc[j]);
                acc[j] = fmaf(xx.x, wr0, acc[j]);
                acc[j] = fmaf(xx.y, wr1, acc[j]);
                acc[j] = fmaf(xx.z, wr2, acc[j]);
                acc[j] = fmaf(xx.w, wr3, acc[j]);
                if (MODE == 0) {
                    acc2[j] = fmaf(xx.x, we0, acc2[j]);
                    acc2[j] = fmaf(xx.y, we1, acc2[j]);
                    acc2[j] = fmaf(xx.z, we2, acc2[j]);
                    acc2[j] = fmaf(xx.w, we3, acc2[j]);
                }
            }
        }

        #pragma unroll
        for (int j = 0; j < NPT; j++) {
            float s = acc[j], s2 = acc[j] * acc[j];
            #pragma unroll
            for (int o = 16; o > 0; o >>= 1) {
                s += __shfl_xor_sync(0xFFFFFFFFu, s, o);
                s2 += __shfl_xor_sync(0xFFFFFFFFu, s2, o);
            }
            if (lane == 0) {
                sRed[grp][half][j][0] = s;
                sRed[grp][half][j][1] = s2;
            }
        }
        __syncthreads();

        #pragma unroll
        for (int j = 0; j < NPT; j++) {
            float sum = sRed[grp][0][j][0] + sRed[grp][1][j][0];
            float sum2 = sRed[grp][0][j][1] + sRed[grp][1][j][1];
            float mu = sum * (1.0f / 64.0f);
            float var = sum2 * (1.0f / 64.0f) - mu * mu;
            float rstd = rsqrtf(var + EPS);
            float y = (acc[j] - mu) * rstd * gv + bev;
            y = fmaxf(y, 0.f);
            if (MODE == 0) y += acc2[j];
            else           y += sX[nb + j][col];

            if (MODE != 2) {
                int n = base + nb + j;
                if (n < nNodes) xout[(size_t)n * D + col] = y;
            } else {
                sA[nb + j][col] = y;
            }
        }

        if (MODE == 2) {
            __syncthreads();
            float acc3[NPT];
            #pragma unroll
            for (int j = 0; j < NPT; j++) acc3[j] = bev2;
            #pragma unroll 4
            for (int k4 = 0; k4 < D / 4; k4++) {
                int k = k4 * 4;
                float w0 = sWe[(k + 0) * D + col];
                float w1 = sWe[(k + 1) * D + col];
                float w2 = sWe[(k + 2) * D + col];
                float w3 = sWe[(k + 3) * D + col];
                #pragma unroll
                for (int j = 0; j < NPT; j++) {
                    float4 yy = ((const float4*)sA[nb + j])[k4];
                    acc3[j] = fmaf(yy.x, w0, acc3[j]);
                    acc3[j] = fmaf(yy.y, w1, acc3[j]);
                    acc3[j] = fmaf(yy.z, w2, acc3[j]);
                    acc3[j] = fmaf(yy.w, w3, acc3[j]);
                }
            }
            #pragma unroll
            for (int j = 0; j < NPT; j++) {
                int n = base + nb + j;
                if (n < nNodes) xout[(size_t)n * D + col] = acc3[j];
            }
        }
    }
}

// ---------------------------------------------------------------------------
extern "C" void kernel_launch(void* const* d_in, const int* in_sizes, int n_in,
                              void* d_out, int out_size) {
    const float* x     = (const float*)d_in[0];
    const int*   esrc  = (const int*)d_in[1];
    const int*   edst  = (const int*)d_in[2];
    const float* w_l   = (const float*)d_in[3];
    const float* b_l   = (const float*)d_in[4];
    const float* w_r   = (const float*)d_in[5];
    const float* gamma = (const float*)d_in[6];
    const float* beta  = (const float*)d_in[7];
    const float* w_res = (const float*)d_in[8];
    const float* b_res = (const float*)d_in[9];
    const float* w_fc  = (const float*)d_in[10];
    const float* b_fc  = (const float*)d_in[11];
    float* out = (float*)d_out;

    int N = in_sizes[0] / D;
    int E = in_sizes[1];

    const int T = 256;
    const size_t SMEM_NODE = 2 * D * D * sizeof(float);  // 32KB dynamic
    const int BLK_FUSED = 444;   // 3 blocks/SM at ~65KB total smem
    const int BLK_MID   = 592;   // 4 blocks/SM at ~49KB total smem
    int NB = (N + 1 + 1023) / 1024;         // scan blocks (covers idx N)
    int aggBlocks = (N + 15) / 16;

    static bool attr_done = false;
    if (!attr_done) {
        cudaFuncSetAttribute(node_kernel<0>,
                             cudaFuncAttributeMaxDynamicSharedMemorySize,
                             (int)SMEM_NODE);
        cudaFuncSetAttribute(node_kernel<1>,
                             cudaFuncAttributeMaxDynamicSharedMemorySize,
                             (int)SMEM_NODE);
        cudaFuncSetAttribute(node_kernel<2>,
                             cudaFuncAttributeMaxDynamicSharedMemorySize,
                             (int)SMEM_NODE);
        attr_done = true;
    }

    // --- CSR build (once per call) ---
    zcnt_kernel<<<(N + T - 1) / T, T>>>(N);
    deg_kernel<<<(E + T - 1) / T, T>>>(edst, E);
    scanA_kernel<<<NB, T>>>(N);
    scanB_kernel<<<1, T>>>(NB);
    scanC_kernel<<<NB, T>>>(N);
    fill_kernel<<<(E + T - 1) / T, T>>>(esrc, edst, E);

    // Layer 0: pull-aggregate(x); node (fused residual projection) -> g_xa
    agg_kernel<BUF_EXT><<<aggBlocks, T>>>(x, N);
    node_kernel<0><<<BLK_FUSED, T, SMEM_NODE>>>(
        x, nullptr, w_l, b_l, w_r, gamma, beta, w_res, b_res, N);

    // Layer 1: g_xa -> g_xb
    agg_kernel<BUF_XA><<<aggBlocks, T>>>(nullptr, N);
    node_kernel<1><<<BLK_MID, T, SMEM_NODE>>>(
        nullptr, nullptr, w_l + D * D, b_l + D, w_r + D * D,
        gamma + D, beta + D, nullptr, nullptr, N);

    // Layer 2 + final FC: writes d_out directly
    agg_kernel<BUF_XB><<<aggBlocks, T>>>(nullptr, N);
    node_kernel<2><<<BLK_FUSED, T, SMEM_NODE>>>(
        nullptr, out, w_l + 2 * D * D, b_l + 2 * D, w_r + 2 * D * D,
        gamma + 2 * D, beta + 2 * D, w_fc, b_fc, N);
}